// round 9
// baseline (speedup 1.0000x reference)
#include <cuda_runtime.h>
#include <cuda_fp16.h>
#include <cstdint>

// ---------------------------------------------------------------------------
// Problem constants
// ---------------------------------------------------------------------------
#define B_   8
#define C_   256
#define N_   4096
#define G_   8
#define CPG_ 32
#define EPS_ 1e-5f
#define QSCALE_ 0.09016844270216718f   // log2(e)/sqrt(C)

// ---------------------------------------------------------------------------
// Device scratch
// ---------------------------------------------------------------------------
__device__ __half g_xh[(size_t)B_ * N_ * C_];    // GN-applied x, token-major
__device__ __half g_qh[(size_t)B_ * N_ * C_];    // Q token-major, pre-scaled
__device__ __half g_kh[(size_t)B_ * N_ * C_];    // K token-major
__device__ __half g_vh[(size_t)B_ * C_ * N_];    // V channel-major
__device__ __half g_oh[(size_t)B_ * N_ * C_];    // attention out, token-major
__device__ __half g_wqh[3 * C_ * C_];            // w_qkv fp16 [o][c]
__device__ __half g_woh[C_ * C_];                // w_out fp16 [o][c]
__device__ float  g_fs[B_ * C_];
__device__ float  g_fb[B_ * C_];

// ---------------------------------------------------------------------------
// Helpers
// ---------------------------------------------------------------------------
__device__ __forceinline__ void mma_f16(float* c,
    uint32_t a0, uint32_t a1, uint32_t a2, uint32_t a3,
    uint32_t b0, uint32_t b1)
{
    asm volatile(
        "mma.sync.aligned.m16n8k16.row.col.f32.f16.f16.f32 "
        "{%0,%1,%2,%3}, {%4,%5,%6,%7}, {%8,%9}, {%0,%1,%2,%3};"
        : "+f"(c[0]), "+f"(c[1]), "+f"(c[2]), "+f"(c[3])
        : "r"(a0), "r"(a1), "r"(a2), "r"(a3), "r"(b0), "r"(b1));
}
__device__ __forceinline__ float ex2f(float x) {
    float r;
    asm("ex2.approx.ftz.f32 %0, %1;" : "=f"(r) : "f"(x));
    return r;
}
__device__ __forceinline__ uint32_t fp2h2(float lo, float hi) {
    __half2 h = __floats2half2_rn(lo, hi);
    return *reinterpret_cast<uint32_t*>(&h);
}
__device__ __forceinline__ uint32_t ldh2(const __half* p) {
    return *reinterpret_cast<const uint32_t*>(p);
}
__device__ __forceinline__ uint32_t smem_u32(const void* p) {
    uint32_t a;
    asm("{ .reg .u64 t; cvta.to.shared.u64 t, %1; cvt.u32.u64 %0, t; }"
        : "=r"(a) : "l"(p));
    return a;
}
__device__ __forceinline__ void cp16(uint32_t dst, const void* src) {
    asm volatile("cp.async.cg.shared.global [%0], [%1], 16;"
                 :: "r"(dst), "l"(src) : "memory");
}
#define CP_COMMIT() asm volatile("cp.async.commit_group;" ::: "memory")
#define CP_WAIT1()  asm volatile("cp.async.wait_group 1;" ::: "memory")
#define CP_WAIT0()  asm volatile("cp.async.wait_group 0;" ::: "memory")
#define PAIR_BAR(id) asm volatile("bar.sync %0, 64;" :: "r"(id) : "memory")

// ---------------------------------------------------------------------------
// Kernel 1: GroupNorm stats -> fused per-(b,c) scale/bias
// ---------------------------------------------------------------------------
__global__ __launch_bounds__(256) void gn_stats_kernel(
    const float* __restrict__ x,
    const float* __restrict__ gamma,
    const float* __restrict__ beta)
{
    int b = blockIdx.x >> 3;
    int g = blockIdx.x & 7;
    const float4* p = reinterpret_cast<const float4*>(
        x + ((size_t)(b * C_ + g * CPG_)) * N_);
    float s1 = 0.f, s2 = 0.f;
    for (int i = threadIdx.x; i < 32768; i += 256) {
        float4 v = p[i];
        s1 += (v.x + v.y) + (v.z + v.w);
        s2 += (v.x * v.x + v.y * v.y) + (v.z * v.z + v.w * v.w);
    }
    #pragma unroll
    for (int off = 16; off; off >>= 1) {
        s1 += __shfl_xor_sync(0xffffffffu, s1, off);
        s2 += __shfl_xor_sync(0xffffffffu, s2, off);
    }
    __shared__ float a1[8], a2[8];
    __shared__ float sh_mean, sh_rstd;
    int warp = threadIdx.x >> 5;
    if ((threadIdx.x & 31) == 0) { a1[warp] = s1; a2[warp] = s2; }
    __syncthreads();
    if (threadIdx.x == 0) {
        float t1 = 0.f, t2 = 0.f;
        #pragma unroll
        for (int w = 0; w < 8; w++) { t1 += a1[w]; t2 += a2[w]; }
        float mean = t1 * (1.f / 131072.f);
        float var  = t2 * (1.f / 131072.f) - mean * mean;
        sh_mean = mean;
        sh_rstd = rsqrtf(var + EPS_);
    }
    __syncthreads();
    if (threadIdx.x < CPG_) {
        int c  = g * CPG_ + threadIdx.x;
        float ga = gamma[c];
        float fs = sh_rstd * ga;
        g_fs[b * C_ + c] = fs;
        g_fb[b * C_ + c] = beta[c] - sh_mean * fs;
    }
}

// ---------------------------------------------------------------------------
// Kernel 2a: weights fp32 -> fp16
// ---------------------------------------------------------------------------
__global__ __launch_bounds__(256) void wconv_kernel(
    const float* __restrict__ wq, const float* __restrict__ wo)
{
    int i = blockIdx.x * 256 + threadIdx.x;
    for (int k = i; k < 3 * C_ * C_; k += 65536)
        g_wqh[k] = __float2half(wq[k]);
    if (i < C_ * C_)
        g_woh[i] = __float2half(wo[i]);
}

// ---------------------------------------------------------------------------
// Kernel 2b: xn = GN(x) as fp16 token-major (B, N, C)
// ---------------------------------------------------------------------------
__global__ __launch_bounds__(256) void xn_half_kernel(const float* __restrict__ x)
{
    __shared__ float T[64][65];
    int n0 = blockIdx.x * 256;
    int c0 = blockIdx.y * 64;
    int b  = blockIdx.z;
    int tid = threadIdx.x;
    const float* fsb = g_fs + b * C_;
    const float* fbb = g_fb + b * C_;

    for (int s = 0; s < 4; s++) {
        int nn0 = n0 + s * 64;
        for (int idx = tid; idx < 1024; idx += 256) {
            int cc = idx >> 4, nn4 = (idx & 15) * 4;
            float4 v = *(const float4*)&x[((size_t)(b * C_ + c0 + cc)) * N_ + nn0 + nn4];
            float fs = fsb[c0 + cc], fb = fbb[c0 + cc];
            T[cc][nn4 + 0] = v.x * fs + fb;
            T[cc][nn4 + 1] = v.y * fs + fb;
            T[cc][nn4 + 2] = v.z * fs + fb;
            T[cc][nn4 + 3] = v.w * fs + fb;
        }
        __syncthreads();
        for (int idx = tid; idx < 2048; idx += 256) {
            int nn = idx >> 5, c = (idx & 31) * 2;
            *(uint32_t*)&g_xh[((size_t)b * N_ + nn0 + nn) * C_ + c0 + c] =
                fp2h2(T[c][nn], T[c + 1][nn]);
        }
        __syncthreads();
    }
}

// ---------------------------------------------------------------------------
// Kernel 3: QKV GEMM fp16 mma. CTA = 128 tokens x 64 outputs, K=256.
// grid (N/128, 12, B); type = y>>2. 101KB smem -> 2 CTAs/SM.
// ---------------------------------------------------------------------------
#define AP 264
#define HG_SMEM ((128 * AP + 64 * AP) * 2)   // 101376 B

__global__ __launch_bounds__(256) void qkv_hgemm_kernel(
    const float* __restrict__ bias)
{
    extern __shared__ __align__(16) char smraw[];
    __half* Ah = (__half*)smraw;
    __half* Bh = Ah + 128 * AP;

    int tid = threadIdx.x;
    int w = tid >> 5, lid = tid & 31;
    int g = lid >> 2, t = lid & 3;
    int wrow = w * 16;
    int n0 = blockIdx.x * 128;
    int o0 = blockIdx.y * 64;
    int b  = blockIdx.z;

    const __half* ag = g_xh + ((size_t)b * N_ + n0) * C_;
    const __half* bg = g_wqh + (size_t)o0 * C_;
    for (int idx = tid; idx < 4096; idx += 256) {
        int r = idx >> 5, c8 = idx & 31;
        *(uint4*)(Ah + r * AP + c8 * 8) = *(const uint4*)(ag + (size_t)r * C_ + c8 * 8);
    }
    for (int idx = tid; idx < 2048; idx += 256) {
        int r = idx >> 5, c8 = idx & 31;
        *(uint4*)(Bh + r * AP + c8 * 8) = *(const uint4*)(bg + (size_t)r * C_ + c8 * 8);
    }
    __syncthreads();

    const __half* ar = Ah + (wrow + g) * AP + 2 * t;
    const __half* br = Bh + g * AP + 2 * t;
    float acc[8][4];
    #pragma unroll
    for (int nb = 0; nb < 8; nb++)
        #pragma unroll
        for (int j = 0; j < 4; j++) acc[nb][j] = 0.f;

    #pragma unroll 4
    for (int kk = 0; kk < 16; kk++) {
        uint32_t a0 = ldh2(ar + kk * 16);
        uint32_t a1 = ldh2(ar + 8 * AP + kk * 16);
        uint32_t a2 = ldh2(ar + kk * 16 + 8);
        uint32_t a3 = ldh2(ar + 8 * AP + kk * 16 + 8);
        #pragma unroll
        for (int nb = 0; nb < 8; nb++) {
            uint32_t b0 = ldh2(br + nb * 8 * AP + kk * 16);
            uint32_t b1 = ldh2(br + nb * 8 * AP + kk * 16 + 8);
            mma_f16(acc[nb], a0, a1, a2, a3, b0, b1);
        }
    }

    int type = blockIdx.y >> 2;           // 0 Q, 1 K, 2 V
    int n_lo = n0 + wrow + g;
    float scale = (type == 0) ? QSCALE_ : 1.f;
    #pragma unroll
    for (int nb = 0; nb < 8; nb++) {
        int og = o0 + nb * 8 + 2 * t;
        int oo = og & 255;
        float b0v = bias[og], b1v = bias[og + 1];
        float d0 = (acc[nb][0] + b0v) * scale;
        float d1 = (acc[nb][1] + b1v) * scale;
        float d2 = (acc[nb][2] + b0v) * scale;
        float d3 = (acc[nb][3] + b1v) * scale;
        if (type < 2) {
            __half* dst = (type == 0 ? g_qh : g_kh) + ((size_t)b * N_ + n_lo) * C_ + oo;
            *(uint32_t*)dst = fp2h2(d0, d1);
            *(uint32_t*)(dst + 8 * C_) = fp2h2(d2, d3);
        } else {
            __half* vd = g_vh + ((size_t)b * C_ + oo) * N_;
            vd[n_lo]            = __float2half(d0);
            vd[N_ + n_lo]       = __float2half(d1);
            vd[n_lo + 8]        = __float2half(d2);
            vd[N_ + n_lo + 8]   = __float2half(d3);
        }
    }
}

// ---------------------------------------------------------------------------
// Kernel 4: flash attention, 512 threads / 16 warps, warp-pair design.
// Pair p = w>>1 owns rows [16p,16p+16); h = w&1 splits S cols / O channels.
// cp.async double-buffered K/V. 149KB smem, 1 CTA/SM, 4 warps/SMSP.
// ---------------------------------------------------------------------------
#define QPH 264
#define KPH 264
#define VPH 40
#define PPH 40
#define QWH (128 * QPH)
#define KWH (32 * KPH)
#define VWH (256 * VPH)
#define PWH (128 * PPH)
#define FL_SMEM ((QWH + 2 * KWH + 2 * VWH + PWH) * 2)   // 152576 B

__global__ void __launch_bounds__(512, 1) flash_kernel()
{
    extern __shared__ __align__(16) char smraw[];
    __half* Qh  = (__half*)smraw;
    __half* Kb0 = Qh + QWH;
    __half* Kb1 = Kb0 + KWH;
    __half* Vb0 = Kb1 + KWH;
    __half* Vb1 = Vb0 + VWH;
    __half* Ph  = Vb1 + VWH;
    __shared__ float ls[2][128];
    uint32_t sb = smem_u32(smraw);
    uint32_t ka[2] = { sb + QWH * 2, sb + (QWH + KWH) * 2 };
    uint32_t va[2] = { sb + (QWH + 2 * KWH) * 2, sb + (QWH + 2 * KWH + VWH) * 2 };

    int tid = threadIdx.x;
    int w   = tid >> 5;
    int lid = tid & 31;
    int g   = lid >> 2;
    int t   = lid & 3;
    int p   = w >> 1;                    // pair / row-group 0..7
    int h   = w & 1;                     // half: S cols / O channels
    int wrow = p * 16;
    int b   = blockIdx.y;
    int n0  = blockIdx.x * 128;

    const __half* qg = g_qh + ((size_t)b * N_ + n0) * C_;
    const __half* kg = g_kh + (size_t)b * N_ * C_;
    const __half* vg = g_vh + (size_t)b * C_ * N_;

    // cp.async coords: 512 threads, 2 x 16B chunks per tile each
    int kr = tid >> 5, kc8 = tid & 31;   // K rows kr, kr+16
    int vc = tid >> 2, vq = tid & 3;     // V chans vc, vc+128

    // prologue: tile 0
    {
        #pragma unroll
        for (int rr = 0; rr < 32; rr += 16)
            cp16(ka[0] + ((kr + rr) * KPH + kc8 * 8) * 2,
                 kg + (size_t)(kr + rr) * C_ + kc8 * 8);
        #pragma unroll
        for (int cc = 0; cc < 256; cc += 128)
            cp16(va[0] + ((vc + cc) * VPH + vq * 8) * 2,
                 vg + (size_t)(vc + cc) * N_ + vq * 8);
        CP_COMMIT();
    }

    // Q fill (overlaps tile-0 arrival)
    for (int idx = tid; idx < 4096; idx += 512) {
        int r = idx >> 5, c8 = idx & 31;
        *(uint4*)(Qh + r * QPH + c8 * 8) =
            *(const uint4*)(qg + (size_t)r * C_ + c8 * 8);
    }

    const __half* qrow = Qh + (wrow + g) * QPH + 2 * t;
    const __half* kr0 = Kb0 + (h * 16 + g) * KPH + 2 * t;
    const __half* kr1 = Kb1 + (h * 16 + g) * KPH + 2 * t;
    __half* pst = Ph + (wrow + g) * PPH + h * 16 + 2 * t;   // P store (own cols)
    const __half* prd = Ph + (wrow + g) * PPH + 2 * t;      // P read (full K)

    float Oacc[16][4];
    #pragma unroll
    for (int nb = 0; nb < 16; nb++)
        #pragma unroll
        for (int j = 0; j < 4; j++) Oacc[nb][j] = 0.f;
    float lsum_lo = 0.f, lsum_hi = 0.f;

    for (int i = 0; i < 128; i++) {
        __syncthreads();
        if (i < 127) {
            int j = i + 1, bf = j & 1;
            #pragma unroll
            for (int rr = 0; rr < 32; rr += 16)
                cp16(ka[bf] + ((kr + rr) * KPH + kc8 * 8) * 2,
                     kg + (size_t)(j * 32 + kr + rr) * C_ + kc8 * 8);
            #pragma unroll
            for (int cc = 0; cc < 256; cc += 128)
                cp16(va[bf] + ((vc + cc) * VPH + vq * 8) * 2,
                     vg + (size_t)(vc + cc) * N_ + j * 32 + vq * 8);
            CP_COMMIT();
            CP_WAIT1();
        } else {
            CP_WAIT0();
        }
        __syncthreads();

        const __half* krow = (i & 1) ? kr1 : kr0;
        const __half* Vbuf = (i & 1) ? Vb1 : Vb0;

        // S = Q @ K^T : 16 rows x 16 cols (this warp's half)
        float s[2][4];
        #pragma unroll
        for (int nb = 0; nb < 2; nb++)
            #pragma unroll
            for (int j = 0; j < 4; j++) s[nb][j] = 0.f;
        #pragma unroll 4
        for (int kk = 0; kk < 16; kk++) {
            uint32_t a0 = ldh2(qrow + kk * 16);
            uint32_t a1 = ldh2(qrow + 8 * QPH + kk * 16);
            uint32_t a2 = ldh2(qrow + kk * 16 + 8);
            uint32_t a3 = ldh2(qrow + 8 * QPH + kk * 16 + 8);
            #pragma unroll
            for (int nb = 0; nb < 2; nb++) {
                uint32_t b0 = ldh2(krow + nb * 8 * KPH + kk * 16);
                uint32_t b1 = ldh2(krow + nb * 8 * KPH + kk * 16 + 8);
                mma_f16(s[nb], a0, a1, a2, a3, b0, b1);
            }
        }

        // P = exp2(S) for own cols
        #pragma unroll
        for (int nb = 0; nb < 2; nb++) {
            float e0 = ex2f(s[nb][0]);
            float e1 = ex2f(s[nb][1]);
            float e2 = ex2f(s[nb][2]);
            float e3 = ex2f(s[nb][3]);
            lsum_lo += e0 + e1;
            lsum_hi += e2 + e3;
            *(uint32_t*)(pst + nb * 8)           = fp2h2(e0, e1);
            *(uint32_t*)(pst + 8 * PPH + nb * 8) = fp2h2(e2, e3);
        }
        PAIR_BAR(1 + p);

        // O += P @ V : 16 rows x 128 channels (this warp's half), K=32
        uint32_t pa[2][4];
        #pragma unroll
        for (int k2 = 0; k2 < 2; k2++) {
            pa[k2][0] = ldh2(prd + k2 * 16);
            pa[k2][1] = ldh2(prd + 8 * PPH + k2 * 16);
            pa[k2][2] = ldh2(prd + k2 * 16 + 8);
            pa[k2][3] = ldh2(prd + 8 * PPH + k2 * 16 + 8);
        }
        #pragma unroll 8
        for (int nb = 0; nb < 16; nb++) {
            const __half* vb = Vbuf + (h * 128 + nb * 8 + g) * VPH + 2 * t;
            uint32_t b0 = ldh2(vb);
            uint32_t b1 = ldh2(vb + 8);
            mma_f16(Oacc[nb], pa[0][0], pa[0][1], pa[0][2], pa[0][3], b0, b1);
            b0 = ldh2(vb + 16);
            b1 = ldh2(vb + 24);
            mma_f16(Oacc[nb], pa[1][0], pa[1][1], pa[1][2], pa[1][3], b0, b1);
        }
    }

    // combine row sums: lane-reduce over t, then across the pair via smem
    lsum_lo += __shfl_xor_sync(0xffffffffu, lsum_lo, 1);
    lsum_lo += __shfl_xor_sync(0xffffffffu, lsum_lo, 2);
    lsum_hi += __shfl_xor_sync(0xffffffffu, lsum_hi, 1);
    lsum_hi += __shfl_xor_sync(0xffffffffu, lsum_hi, 2);
    if (t == 0) {
        ls[h][wrow + g]     = lsum_lo;
        ls[h][wrow + g + 8] = lsum_hi;
    }
    __syncthreads();
    float inv_lo = 1.f / (ls[0][wrow + g]     + ls[1][wrow + g]);
    float inv_hi = 1.f / (ls[0][wrow + g + 8] + ls[1][wrow + g + 8]);

    // epilogue: fp16 O token-major, half2 stores (own 128 channels)
    __half* od = g_oh + ((size_t)b * N_ + n0 + wrow + g) * C_;
    #pragma unroll
    for (int nb = 0; nb < 16; nb++) {
        int c = h * 128 + nb * 8 + 2 * t;
        *(uint32_t*)(od + c) = fp2h2(Oacc[nb][0] * inv_lo, Oacc[nb][1] * inv_lo);
        *(uint32_t*)(od + 8 * C_ + c) = fp2h2(Oacc[nb][2] * inv_hi, Oacc[nb][3] * inv_hi);
    }
}

// ---------------------------------------------------------------------------
// Kernel 5: output projection fp16 mma + bias + residual.
// CTA = 128 tokens x 64 outputs; grid (N/128, 4, B). 2 CTAs/SM.
// ---------------------------------------------------------------------------
__global__ __launch_bounds__(256) void proj_hgemm_kernel(
    const float* __restrict__ bias,
    const float* __restrict__ x,
    float* __restrict__ out)
{
    extern __shared__ __align__(16) char smraw[];
    __half* Ah = (__half*)smraw;
    __half* Bh = Ah + 128 * AP;
    float* Ts  = (float*)smraw;          // reused after compute: 64 x 136

    int tid = threadIdx.x;
    int w = tid >> 5, lid = tid & 31;
    int g = lid >> 2, t = lid & 3;
    int wrow = w * 16;
    int n0 = blockIdx.x * 128;
    int o0 = blockIdx.y * 64;
    int b  = blockIdx.z;

    const __half* ag = g_oh + ((size_t)b * N_ + n0) * C_;
    const __half* bg = g_woh + (size_t)o0 * C_;
    for (int idx = tid; idx < 4096; idx += 256) {
        int r = idx >> 5, c8 = idx & 31;
        *(uint4*)(Ah + r * AP + c8 * 8) = *(const uint4*)(ag + (size_t)r * C_ + c8 * 8);
    }
    for (int idx = tid; idx < 2048; idx += 256) {
        int r = idx >> 5, c8 = idx & 31;
        *(uint4*)(Bh + r * AP + c8 * 8) = *(const uint4*)(bg + (size_t)r * C_ + c8 * 8);
    }
    __syncthreads();

    const __half* ar = Ah + (wrow + g) * AP + 2 * t;
    const __half* br = Bh + g * AP + 2 * t;
    float acc[8][4];
    #pragma unroll
    for (int nb = 0; nb < 8; nb++)
        #pragma unroll
        for (int j = 0; j < 4; j++) acc[nb][j] = 0.f;

    #pragma unroll 4
    for (int kk = 0; kk < 16; kk++) {
        uint32_t a0 = ldh2(ar + kk * 16);
        uint32_t a1 = ldh2(ar + 8 * AP + kk * 16);
        uint32_t a2 = ldh2(ar + kk * 16 + 8);
        uint32_t a3 = ldh2(ar + 8 * AP + kk * 16 + 8);
        #pragma unroll
        for (int nb = 0; nb < 8; nb++) {
            uint32_t b0 = ldh2(br + nb * 8 * AP + kk * 16);
            uint32_t b1 = ldh2(br + nb * 8 * AP + kk * 16 + 8);
            mma_f16(acc[nb], a0, a1, a2, a3, b0, b1);
        }
    }

    // stage D transposed [o_local][token] in fp32
    __syncthreads();
    #pragma unroll
    for (int nb = 0; nb < 8; nb++) {
        int ol = nb * 8 + 2 * t;
        Ts[ol * 136 + wrow + g]           = acc[nb][0];
        Ts[(ol + 1) * 136 + wrow + g]     = acc[nb][1];
        Ts[ol * 136 + wrow + g + 8]       = acc[nb][2];
        Ts[(ol + 1) * 136 + wrow + g + 8] = acc[nb][3];
    }
    __syncthreads();

    for (int idx = tid; idx < 2048; idx += 256) {
        int o = idx >> 5, n4 = (idx & 31) * 4;
        int og = o0 + o;
        float bo = bias[og];
        size_t base = ((size_t)b * C_ + og) * N_ + n0 + n4;
        float4 res = *(const float4*)&x[base];
        float4 d   = *(const float4*)&Ts[o * 136 + n4];
        float4 r = make_float4(d.x + bo + res.x, d.y + bo + res.y,
                               d.z + bo + res.z, d.w + bo + res.w);
        *(float4*)&out[base] = r;
    }
}

// ---------------------------------------------------------------------------
// Launch
// ---------------------------------------------------------------------------
extern "C" void kernel_launch(void* const* d_in, const int* in_sizes, int n_in,
                              void* d_out, int out_size)
{
    const float* x        = (const float*)d_in[0];
    const float* gn_scale = (const float*)d_in[1];
    const float* gn_bias  = (const float*)d_in[2];
    const float* w_qkv    = (const float*)d_in[3];
    const float* b_qkv    = (const float*)d_in[4];
    const float* w_out    = (const float*)d_in[5];
    const float* b_out    = (const float*)d_in[6];
    float* out = (float*)d_out;

    cudaFuncSetAttribute(flash_kernel,
                         cudaFuncAttributeMaxDynamicSharedMemorySize, FL_SMEM);
    cudaFuncSetAttribute(qkv_hgemm_kernel,
                         cudaFuncAttributeMaxDynamicSharedMemorySize, HG_SMEM);
    cudaFuncSetAttribute(proj_hgemm_kernel,
                         cudaFuncAttributeMaxDynamicSharedMemorySize, HG_SMEM);

    wconv_kernel<<<256, 256>>>(w_qkv, w_out);
    gn_stats_kernel<<<B_ * G_, 256>>>(x, gn_scale, gn_bias);
    xn_half_kernel<<<dim3(N_ / 256, C_ / 64, B_), 256>>>(x);
    qkv_hgemm_kernel<<<dim3(N_ / 128, 12, B_), 256, HG_SMEM>>>(b_qkv);
    flash_kernel<<<dim3(N_ / 128, B_), 512, FL_SMEM>>>();
    proj_hgemm_kernel<<<dim3(N_ / 128, 4, B_), 256, HG_SMEM>>>(b_out, x, out);
}

// round 10
// speedup vs baseline: 1.0824x; 1.0824x over previous
#include <cuda_runtime.h>
#include <cuda_fp16.h>
#include <cstdint>

// ---------------------------------------------------------------------------
// Problem constants
// ---------------------------------------------------------------------------
#define B_   8
#define C_   256
#define N_   4096
#define G_   8
#define CPG_ 32
#define EPS_ 1e-5f
#define QSCALE_ 0.09016844270216718f   // log2(e)/sqrt(C)

// ---------------------------------------------------------------------------
// Device scratch
// ---------------------------------------------------------------------------
__device__ __half g_xh[(size_t)B_ * N_ * C_];    // GN-applied x, token-major
__device__ __half g_qh[(size_t)B_ * N_ * C_];    // Q token-major, pre-scaled
__device__ __half g_kh[(size_t)B_ * N_ * C_];    // K token-major
__device__ __half g_vh[(size_t)B_ * C_ * N_];    // V channel-major
__device__ __half g_oh[(size_t)B_ * N_ * C_];    // attention out, token-major
__device__ __half g_wqh[3 * C_ * C_];            // w_qkv fp16 [o][c]
__device__ __half g_woh[C_ * C_];                // w_out fp16 [o][c]
__device__ float  g_fs[B_ * C_];
__device__ float  g_fb[B_ * C_];

// ---------------------------------------------------------------------------
// Helpers
// ---------------------------------------------------------------------------
__device__ __forceinline__ void mma_f16(float* c,
    uint32_t a0, uint32_t a1, uint32_t a2, uint32_t a3,
    uint32_t b0, uint32_t b1)
{
    asm volatile(
        "mma.sync.aligned.m16n8k16.row.col.f32.f16.f16.f32 "
        "{%0,%1,%2,%3}, {%4,%5,%6,%7}, {%8,%9}, {%0,%1,%2,%3};"
        : "+f"(c[0]), "+f"(c[1]), "+f"(c[2]), "+f"(c[3])
        : "r"(a0), "r"(a1), "r"(a2), "r"(a3), "r"(b0), "r"(b1));
}
__device__ __forceinline__ void ldsm4(uint32_t& r0, uint32_t& r1,
                                      uint32_t& r2, uint32_t& r3, uint32_t addr)
{
    asm volatile("ldmatrix.sync.aligned.m8n8.x4.shared.b16 {%0,%1,%2,%3}, [%4];"
        : "=r"(r0), "=r"(r1), "=r"(r2), "=r"(r3) : "r"(addr));
}
__device__ __forceinline__ float ex2f(float x) {
    float r;
    asm("ex2.approx.ftz.f32 %0, %1;" : "=f"(r) : "f"(x));
    return r;
}
__device__ __forceinline__ uint32_t fp2h2(float lo, float hi) {
    __half2 h = __floats2half2_rn(lo, hi);
    return *reinterpret_cast<uint32_t*>(&h);
}
__device__ __forceinline__ uint32_t smem_u32(const void* p) {
    uint32_t a;
    asm("{ .reg .u64 t; cvta.to.shared.u64 t, %1; cvt.u32.u64 %0, t; }"
        : "=r"(a) : "l"(p));
    return a;
}
__device__ __forceinline__ void cp16(uint32_t dst, const void* src) {
    asm volatile("cp.async.cg.shared.global [%0], [%1], 16;"
                 :: "r"(dst), "l"(src) : "memory");
}
#define CP_COMMIT() asm volatile("cp.async.commit_group;" ::: "memory")
#define CP_WAIT1()  asm volatile("cp.async.wait_group 1;" ::: "memory")
#define CP_WAIT0()  asm volatile("cp.async.wait_group 0;" ::: "memory")

// ---------------------------------------------------------------------------
// Kernel 1: GroupNorm stats -> fused per-(b,c) scale/bias
// ---------------------------------------------------------------------------
__global__ __launch_bounds__(256) void gn_stats_kernel(
    const float* __restrict__ x,
    const float* __restrict__ gamma,
    const float* __restrict__ beta)
{
    int b = blockIdx.x >> 3;
    int g = blockIdx.x & 7;
    const float4* p = reinterpret_cast<const float4*>(
        x + ((size_t)(b * C_ + g * CPG_)) * N_);
    float s1 = 0.f, s2 = 0.f;
    for (int i = threadIdx.x; i < 32768; i += 256) {
        float4 v = p[i];
        s1 += (v.x + v.y) + (v.z + v.w);
        s2 += (v.x * v.x + v.y * v.y) + (v.z * v.z + v.w * v.w);
    }
    #pragma unroll
    for (int off = 16; off; off >>= 1) {
        s1 += __shfl_xor_sync(0xffffffffu, s1, off);
        s2 += __shfl_xor_sync(0xffffffffu, s2, off);
    }
    __shared__ float a1[8], a2[8];
    __shared__ float sh_mean, sh_rstd;
    int warp = threadIdx.x >> 5;
    if ((threadIdx.x & 31) == 0) { a1[warp] = s1; a2[warp] = s2; }
    __syncthreads();
    if (threadIdx.x == 0) {
        float t1 = 0.f, t2 = 0.f;
        #pragma unroll
        for (int w = 0; w < 8; w++) { t1 += a1[w]; t2 += a2[w]; }
        float mean = t1 * (1.f / 131072.f);
        float var  = t2 * (1.f / 131072.f) - mean * mean;
        sh_mean = mean;
        sh_rstd = rsqrtf(var + EPS_);
    }
    __syncthreads();
    if (threadIdx.x < CPG_) {
        int c  = g * CPG_ + threadIdx.x;
        float ga = gamma[c];
        float fs = sh_rstd * ga;
        g_fs[b * C_ + c] = fs;
        g_fb[b * C_ + c] = beta[c] - sh_mean * fs;
    }
}

// ---------------------------------------------------------------------------
// Kernel 2a: weights fp32 -> fp16
// ---------------------------------------------------------------------------
__global__ __launch_bounds__(256) void wconv_kernel(
    const float* __restrict__ wq, const float* __restrict__ wo)
{
    int i = blockIdx.x * 256 + threadIdx.x;
    for (int k = i; k < 3 * C_ * C_; k += 65536)
        g_wqh[k] = __float2half(wq[k]);
    if (i < C_ * C_)
        g_woh[i] = __float2half(wo[i]);
}

// ---------------------------------------------------------------------------
// Kernel 2b: xn = GN(x) as fp16 token-major (B, N, C)
// ---------------------------------------------------------------------------
__global__ __launch_bounds__(256) void xn_half_kernel(const float* __restrict__ x)
{
    __shared__ float T[64][65];
    int n0 = blockIdx.x * 256;
    int c0 = blockIdx.y * 64;
    int b  = blockIdx.z;
    int tid = threadIdx.x;
    const float* fsb = g_fs + b * C_;
    const float* fbb = g_fb + b * C_;

    for (int s = 0; s < 4; s++) {
        int nn0 = n0 + s * 64;
        for (int idx = tid; idx < 1024; idx += 256) {
            int cc = idx >> 4, nn4 = (idx & 15) * 4;
            float4 v = *(const float4*)&x[((size_t)(b * C_ + c0 + cc)) * N_ + nn0 + nn4];
            float fs = fsb[c0 + cc], fb = fbb[c0 + cc];
            T[cc][nn4 + 0] = v.x * fs + fb;
            T[cc][nn4 + 1] = v.y * fs + fb;
            T[cc][nn4 + 2] = v.z * fs + fb;
            T[cc][nn4 + 3] = v.w * fs + fb;
        }
        __syncthreads();
        for (int idx = tid; idx < 2048; idx += 256) {
            int nn = idx >> 5, c = (idx & 31) * 2;
            *(uint32_t*)&g_xh[((size_t)b * N_ + nn0 + nn) * C_ + c0 + c] =
                fp2h2(T[c][nn], T[c + 1][nn]);
        }
        __syncthreads();
    }
}

// ---------------------------------------------------------------------------
// Kernel 3: QKV GEMM fp16 mma + ldmatrix. CTA = 128 tokens x 64 outputs.
// grid (N/128, 12, B); type = y>>2. 101KB smem -> 2 CTAs/SM.
// ---------------------------------------------------------------------------
#define AP 264
#define HG_SMEM ((128 * AP + 64 * AP) * 2)   // 101376 B

__global__ __launch_bounds__(256) void qkv_hgemm_kernel(
    const float* __restrict__ bias)
{
    extern __shared__ __align__(16) char smraw[];
    __half* Ah = (__half*)smraw;
    __half* Bh = Ah + 128 * AP;

    int tid = threadIdx.x;
    int w = tid >> 5, lid = tid & 31;
    int g = lid >> 2, t = lid & 3;
    int wrow = w * 16;
    int n0 = blockIdx.x * 128;
    int o0 = blockIdx.y * 64;
    int b  = blockIdx.z;

    const __half* ag = g_xh + ((size_t)b * N_ + n0) * C_;
    const __half* bg = g_wqh + (size_t)o0 * C_;
    for (int idx = tid; idx < 4096; idx += 256) {
        int r = idx >> 5, c8 = idx & 31;
        *(uint4*)(Ah + r * AP + c8 * 8) = *(const uint4*)(ag + (size_t)r * C_ + c8 * 8);
    }
    for (int idx = tid; idx < 2048; idx += 256) {
        int r = idx >> 5, c8 = idx & 31;
        *(uint4*)(Bh + r * AP + c8 * 8) = *(const uint4*)(bg + (size_t)r * C_ + c8 * 8);
    }
    __syncthreads();

    // ldmatrix lane addresses
    uint32_t aa = smem_u32(Ah) +
        (uint32_t)(((wrow + (lid & 15)) * AP + (lid >> 4) * 8) * 2);
    uint32_t bb = smem_u32(Bh) +
        (uint32_t)(((((lid & 7) + ((lid >> 4) & 1) * 8)) * AP + ((lid >> 3) & 1) * 8) * 2);

    float acc[8][4];
    #pragma unroll
    for (int nb = 0; nb < 8; nb++)
        #pragma unroll
        for (int j = 0; j < 4; j++) acc[nb][j] = 0.f;

    #pragma unroll 4
    for (int kk = 0; kk < 16; kk++) {
        uint32_t a0, a1, a2, a3;
        ldsm4(a0, a1, a2, a3, aa + kk * 32);
        #pragma unroll
        for (int nbp = 0; nbp < 4; nbp++) {
            uint32_t b0, b1, b2, b3;
            ldsm4(b0, b1, b2, b3, bb + (nbp * 16 * AP + kk * 16) * 2);
            mma_f16(acc[2 * nbp],     a0, a1, a2, a3, b0, b1);
            mma_f16(acc[2 * nbp + 1], a0, a1, a2, a3, b2, b3);
        }
    }

    int type = blockIdx.y >> 2;           // 0 Q, 1 K, 2 V
    int n_lo = n0 + wrow + g;
    float scale = (type == 0) ? QSCALE_ : 1.f;
    #pragma unroll
    for (int nb = 0; nb < 8; nb++) {
        int og = o0 + nb * 8 + 2 * t;
        int oo = og & 255;
        float b0v = bias[og], b1v = bias[og + 1];
        float d0 = (acc[nb][0] + b0v) * scale;
        float d1 = (acc[nb][1] + b1v) * scale;
        float d2 = (acc[nb][2] + b0v) * scale;
        float d3 = (acc[nb][3] + b1v) * scale;
        if (type < 2) {
            __half* dst = (type == 0 ? g_qh : g_kh) + ((size_t)b * N_ + n_lo) * C_ + oo;
            *(uint32_t*)dst = fp2h2(d0, d1);
            *(uint32_t*)(dst + 8 * C_) = fp2h2(d2, d3);
        } else {
            __half* vd = g_vh + ((size_t)b * C_ + oo) * N_;
            vd[n_lo]            = __float2half(d0);
            vd[N_ + n_lo]       = __float2half(d1);
            vd[n_lo + 8]        = __float2half(d2);
            vd[N_ + n_lo + 8]   = __float2half(d3);
        }
    }
}

// ---------------------------------------------------------------------------
// Kernel 4: flash attention, 256 thr / 8 warps, ldmatrix fragments,
// 3-stage cp.async ring with ONE __syncthreads per iteration.
// ---------------------------------------------------------------------------
#define QPH 264
#define KPH 264
#define VPH 40
#define PPH 40
#define QWH (128 * QPH)
#define KWH (32 * KPH)
#define VWH (256 * VPH)
#define PWH (128 * PPH)
#define FL_SMEM ((QWH + 3 * KWH + 3 * VWH + PWH) * 2)   // 189952 B

__global__ void __launch_bounds__(256, 1) flash_kernel()
{
    extern __shared__ __align__(16) char smraw[];
    __half* Qh = (__half*)smraw;
    __half* Ph = Qh + QWH + 3 * KWH + 3 * VWH;
    uint32_t sb = smem_u32(smraw);
    uint32_t ka[3], va[3];
    #pragma unroll
    for (int s = 0; s < 3; s++) {
        ka[s] = sb + (QWH + s * KWH) * 2;
        va[s] = sb + (QWH + 3 * KWH + s * VWH) * 2;
    }
    uint32_t pa_base = sb + (uint32_t)((QWH + 3 * KWH + 3 * VWH) * 2);

    int tid = threadIdx.x;
    int w   = tid >> 5;
    int lid = tid & 31;
    int g   = lid >> 2;
    int t   = lid & 3;
    int b   = blockIdx.y;
    int n0  = blockIdx.x * 128;
    int wrow = w * 16;

    const __half* qg = g_qh + ((size_t)b * N_ + n0) * C_;
    const __half* kg = g_kh + (size_t)b * N_ * C_;
    const __half* vg = g_vh + (size_t)b * C_ * N_;

    // cp.async fill coords (8 x 16B per thread per tile)
    int kr = tid >> 5, kc8 = tid & 31;
    int vc = tid >> 2, vq = tid & 3;

    // prologue: tiles 0 and 1
    #pragma unroll
    for (int j = 0; j < 2; j++) {
        #pragma unroll
        for (int rr = 0; rr < 32; rr += 8)
            cp16(ka[j] + ((kr + rr) * KPH + kc8 * 8) * 2,
                 kg + (size_t)(j * 32 + kr + rr) * C_ + kc8 * 8);
        #pragma unroll
        for (int cc = 0; cc < 256; cc += 64)
            cp16(va[j] + ((vc + cc) * VPH + vq * 8) * 2,
                 vg + (size_t)(vc + cc) * N_ + j * 32 + vq * 8);
        CP_COMMIT();
    }

    // Q fill (overlaps prologue arrival)
    for (int idx = tid; idx < 4096; idx += 256) {
        int r = idx >> 5, c8 = idx & 31;
        *(uint4*)(Qh + r * QPH + c8 * 8) =
            *(const uint4*)(qg + (size_t)r * C_ + c8 * 8);
    }

    // ldmatrix lane addresses
    uint32_t qa = sb + (uint32_t)(((wrow + (lid & 15)) * QPH + (lid >> 4) * 8) * 2);
    uint32_t kbo = (uint32_t)(((((lid & 7) + ((lid >> 4) & 1) * 8)) * KPH
                               + ((lid >> 3) & 1) * 8) * 2);
    uint32_t vbo = (uint32_t)(((((lid & 7) + ((lid >> 4) & 1) * 8)) * VPH
                               + ((lid >> 3) & 1) * 8) * 2);
    uint32_t pra = pa_base + (uint32_t)(((wrow + (lid & 15)) * PPH + (lid >> 4) * 8) * 2);
    __half* pst = Ph + (wrow + g) * PPH + 2 * t;

    float Oacc[32][4];
    #pragma unroll
    for (int nb = 0; nb < 32; nb++)
        #pragma unroll
        for (int j = 0; j < 4; j++) Oacc[nb][j] = 0.f;
    float lsum_lo = 0.f, lsum_hi = 0.f;

    int bc = 0, bw = 2;
    for (int i = 0; i < 128; i++) {
        if (i < 127) { CP_WAIT1(); } else { CP_WAIT0(); }
        __syncthreads();
        if (i < 126) {
            int j = i + 2;
            uint32_t kd = ka[bw], vd = va[bw];
            #pragma unroll
            for (int rr = 0; rr < 32; rr += 8)
                cp16(kd + ((kr + rr) * KPH + kc8 * 8) * 2,
                     kg + (size_t)(j * 32 + kr + rr) * C_ + kc8 * 8);
            #pragma unroll
            for (int cc = 0; cc < 256; cc += 64)
                cp16(vd + ((vc + cc) * VPH + vq * 8) * 2,
                     vg + (size_t)(vc + cc) * N_ + j * 32 + vq * 8);
            CP_COMMIT();
        }

        uint32_t kbuf = ka[bc] + kbo;
        uint32_t vbuf = va[bc] + vbo;

        // ---- S = Q @ K^T : 16 rows x 32 keys, K=256
        float s[4][4];
        #pragma unroll
        for (int nb = 0; nb < 4; nb++)
            #pragma unroll
            for (int j = 0; j < 4; j++) s[nb][j] = 0.f;
        #pragma unroll 4
        for (int kk = 0; kk < 16; kk++) {
            uint32_t a0, a1, a2, a3;
            ldsm4(a0, a1, a2, a3, qa + kk * 32);
            #pragma unroll
            for (int nbp = 0; nbp < 2; nbp++) {
                uint32_t b0, b1, b2, b3;
                ldsm4(b0, b1, b2, b3, kbuf + (nbp * 16 * KPH + kk * 16) * 2);
                mma_f16(s[2 * nbp],     a0, a1, a2, a3, b0, b1);
                mma_f16(s[2 * nbp + 1], a0, a1, a2, a3, b2, b3);
            }
        }

        // ---- P = exp2(S)
        #pragma unroll
        for (int nb = 0; nb < 4; nb++) {
            float e0 = ex2f(s[nb][0]);
            float e1 = ex2f(s[nb][1]);
            float e2 = ex2f(s[nb][2]);
            float e3 = ex2f(s[nb][3]);
            lsum_lo += e0 + e1;
            lsum_hi += e2 + e3;
            *(uint32_t*)(pst + nb * 8)           = fp2h2(e0, e1);
            *(uint32_t*)(pst + 8 * PPH + nb * 8) = fp2h2(e2, e3);
        }
        __syncwarp();

        // ---- O += P @ V : 16 rows x 256 channels, K=32
        uint32_t pf[2][4];
        #pragma unroll
        for (int kst = 0; kst < 2; kst++)
            ldsm4(pf[kst][0], pf[kst][1], pf[kst][2], pf[kst][3], pra + kst * 32);
        #pragma unroll 4
        for (int nbp = 0; nbp < 16; nbp++) {
            #pragma unroll
            for (int kst = 0; kst < 2; kst++) {
                uint32_t b0, b1, b2, b3;
                ldsm4(b0, b1, b2, b3, vbuf + (nbp * 16 * VPH + kst * 16) * 2);
                mma_f16(Oacc[2 * nbp],     pf[kst][0], pf[kst][1], pf[kst][2], pf[kst][3], b0, b1);
                mma_f16(Oacc[2 * nbp + 1], pf[kst][0], pf[kst][1], pf[kst][2], pf[kst][3], b2, b3);
            }
        }

        bc = (bc == 2) ? 0 : bc + 1;
        bw = (bw == 2) ? 0 : bw + 1;
    }

    // row-sum reduce across the 4 col-group lanes
    lsum_lo += __shfl_xor_sync(0xffffffffu, lsum_lo, 1);
    lsum_lo += __shfl_xor_sync(0xffffffffu, lsum_lo, 2);
    lsum_hi += __shfl_xor_sync(0xffffffffu, lsum_hi, 1);
    lsum_hi += __shfl_xor_sync(0xffffffffu, lsum_hi, 2);
    float inv_lo = 1.f / lsum_lo;
    float inv_hi = 1.f / lsum_hi;

    // epilogue: fp16 O token-major
    __half* od = g_oh + ((size_t)b * N_ + n0 + wrow + g) * C_;
    #pragma unroll
    for (int nb = 0; nb < 32; nb++) {
        int c = nb * 8 + 2 * t;
        *(uint32_t*)(od + c) = fp2h2(Oacc[nb][0] * inv_lo, Oacc[nb][1] * inv_lo);
        *(uint32_t*)(od + 8 * C_ + c) = fp2h2(Oacc[nb][2] * inv_hi, Oacc[nb][3] * inv_hi);
    }
}

// ---------------------------------------------------------------------------
// Kernel 5: output projection fp16 mma + ldmatrix + bias + residual.
// CTA = 128 tokens x 64 outputs; grid (N/128, 4, B). 2 CTAs/SM.
// ---------------------------------------------------------------------------
__global__ __launch_bounds__(256) void proj_hgemm_kernel(
    const float* __restrict__ bias,
    const float* __restrict__ x,
    float* __restrict__ out)
{
    extern __shared__ __align__(16) char smraw[];
    __half* Ah = (__half*)smraw;
    __half* Bh = Ah + 128 * AP;
    float* Ts  = (float*)smraw;          // reused after compute: 64 x 136

    int tid = threadIdx.x;
    int w = tid >> 5, lid = tid & 31;
    int g = lid >> 2, t = lid & 3;
    int wrow = w * 16;
    int n0 = blockIdx.x * 128;
    int o0 = blockIdx.y * 64;
    int b  = blockIdx.z;

    const __half* ag = g_oh + ((size_t)b * N_ + n0) * C_;
    const __half* bg = g_woh + (size_t)o0 * C_;
    for (int idx = tid; idx < 4096; idx += 256) {
        int r = idx >> 5, c8 = idx & 31;
        *(uint4*)(Ah + r * AP + c8 * 8) = *(const uint4*)(ag + (size_t)r * C_ + c8 * 8);
    }
    for (int idx = tid; idx < 2048; idx += 256) {
        int r = idx >> 5, c8 = idx & 31;
        *(uint4*)(Bh + r * AP + c8 * 8) = *(const uint4*)(bg + (size_t)r * C_ + c8 * 8);
    }
    __syncthreads();

    uint32_t aa = smem_u32(Ah) +
        (uint32_t)(((wrow + (lid & 15)) * AP + (lid >> 4) * 8) * 2);
    uint32_t bb = smem_u32(Bh) +
        (uint32_t)(((((lid & 7) + ((lid >> 4) & 1) * 8)) * AP + ((lid >> 3) & 1) * 8) * 2);

    float acc[8][4];
    #pragma unroll
    for (int nb = 0; nb < 8; nb++)
        #pragma unroll
        for (int j = 0; j < 4; j++) acc[nb][j] = 0.f;

    #pragma unroll 4
    for (int kk = 0; kk < 16; kk++) {
        uint32_t a0, a1, a2, a3;
        ldsm4(a0, a1, a2, a3, aa + kk * 32);
        #pragma unroll
        for (int nbp = 0; nbp < 4; nbp++) {
            uint32_t b0, b1, b2, b3;
            ldsm4(b0, b1, b2, b3, bb + (nbp * 16 * AP + kk * 16) * 2);
            mma_f16(acc[2 * nbp],     a0, a1, a2, a3, b0, b1);
            mma_f16(acc[2 * nbp + 1], a0, a1, a2, a3, b2, b3);
        }
    }

    // stage D transposed [o_local][token] in fp32
    __syncthreads();
    #pragma unroll
    for (int nb = 0; nb < 8; nb++) {
        int ol = nb * 8 + 2 * t;
        Ts[ol * 136 + wrow + g]           = acc[nb][0];
        Ts[(ol + 1) * 136 + wrow + g]     = acc[nb][1];
        Ts[ol * 136 + wrow + g + 8]       = acc[nb][2];
        Ts[(ol + 1) * 136 + wrow + g + 8] = acc[nb][3];
    }
    __syncthreads();

    for (int idx = tid; idx < 2048; idx += 256) {
        int o = idx >> 5, n4 = (idx & 31) * 4;
        int og = o0 + o;
        float bo = bias[og];
        size_t base = ((size_t)b * C_ + og) * N_ + n0 + n4;
        float4 res = *(const float4*)&x[base];
        float4 d   = *(const float4*)&Ts[o * 136 + n4];
        float4 r = make_float4(d.x + bo + res.x, d.y + bo + res.y,
                               d.z + bo + res.z, d.w + bo + res.w);
        *(float4*)&out[base] = r;
    }
}

// ---------------------------------------------------------------------------
// Launch
// ---------------------------------------------------------------------------
extern "C" void kernel_launch(void* const* d_in, const int* in_sizes, int n_in,
                              void* d_out, int out_size)
{
    const float* x        = (const float*)d_in[0];
    const float* gn_scale = (const float*)d_in[1];
    const float* gn_bias  = (const float*)d_in[2];
    const float* w_qkv    = (const float*)d_in[3];
    const float* b_qkv    = (const float*)d_in[4];
    const float* w_out    = (const float*)d_in[5];
    const float* b_out    = (const float*)d_in[6];
    float* out = (float*)d_out;

    cudaFuncSetAttribute(flash_kernel,
                         cudaFuncAttributeMaxDynamicSharedMemorySize, FL_SMEM);
    cudaFuncSetAttribute(qkv_hgemm_kernel,
                         cudaFuncAttributeMaxDynamicSharedMemorySize, HG_SMEM);
    cudaFuncSetAttribute(proj_hgemm_kernel,
                         cudaFuncAttributeMaxDynamicSharedMemorySize, HG_SMEM);

    wconv_kernel<<<256, 256>>>(w_qkv, w_out);
    gn_stats_kernel<<<B_ * G_, 256>>>(x, gn_scale, gn_bias);
    xn_half_kernel<<<dim3(N_ / 256, C_ / 64, B_), 256>>>(x);
    qkv_hgemm_kernel<<<dim3(N_ / 128, 12, B_), 256, HG_SMEM>>>(b_qkv);
    flash_kernel<<<dim3(N_ / 128, B_), 256, FL_SMEM>>>();
    proj_hgemm_kernel<<<dim3(N_ / 128, 4, B_), 256, HG_SMEM>>>(b_out, x, out);
}